// round 10
// baseline (speedup 1.0000x reference)
#include <cuda_runtime.h>

#define BB 32
#define NN 128
#define DD 64
#define HH 128
#define NROWS (BB*NN)   // 4096

typedef unsigned long long u64;

#define PACK2(d, lo, hi)   asm("mov.b64 %0, {%1, %2};" : "=l"(d) : "f"(lo), "f"(hi))
#define UNPACK2(lo, hi, s) asm("mov.b64 {%0, %1}, %2;" : "=f"(lo), "=f"(hi) : "l"(s))
#define FMA2(acc, a, b)    asm("fma.rn.f32x2 %0, %1, %2, %0;" : "+l"(acc) : "l"(a), "l"(b))
#define ADD2(d, a, b)      asm("add.rn.f32x2 %0, %1, %2;" : "=l"(d) : "l"(a), "l"(b))

union F4U { float4 f; u64 u[2]; };

// ---------------- scratch (device globals) ----------------
__device__ float g_AI[BB*NN*HH];   // x @ A1[:d]
__device__ float g_AJ[BB*NN*HH];   // x @ A1[d:] + ab1
__device__ float g_WI[BB*NN*HH];   // x @ W1[:d]
__device__ float g_WJ[BB*NN*HH];   // x @ W1[d:] + b1

// ---------------- per-node projections: 16 rows/block, direct weight reads ----------------
__global__ __launch_bounds__(256, 2)
void proj_kernel(const float* __restrict__ x,
                 const float* __restrict__ A1, const float* __restrict__ W1,
                 const float* __restrict__ b1, const float* __restrict__ ab1) {
    __shared__ __align__(16) float4 xr[16*16];   // 16 rows x 64 cols
    int t = threadIdx.x;
    int col = t & 127;
    int half = t >> 7;
    int row0 = blockIdx.x * 16;
    xr[t] = ((const float4*)x)[row0*16 + t];
    __syncthreads();
    float biasAJ = ab1[col];
    float biasWJ = b1[col];
    float a0[8], a1[8], a2[8], a3[8];
    #pragma unroll
    for (int r = 0; r < 8; ++r) { a0[r]=0.f; a1[r]=0.f; a2[r]=0.f; a3[r]=0.f; }
    #pragma unroll 2
    for (int d4 = 0; d4 < 16; ++d4) {
        float w0x = A1[(d4*4+0)*HH + col], w0y = A1[(d4*4+1)*HH + col];
        float w0z = A1[(d4*4+2)*HH + col], w0w = A1[(d4*4+3)*HH + col];
        float w1x = A1[(64+d4*4+0)*HH + col], w1y = A1[(64+d4*4+1)*HH + col];
        float w1z = A1[(64+d4*4+2)*HH + col], w1w = A1[(64+d4*4+3)*HH + col];
        float w2x = W1[(d4*4+0)*HH + col], w2y = W1[(d4*4+1)*HH + col];
        float w2z = W1[(d4*4+2)*HH + col], w2w = W1[(d4*4+3)*HH + col];
        float w3x = W1[(64+d4*4+0)*HH + col], w3y = W1[(64+d4*4+1)*HH + col];
        float w3z = W1[(64+d4*4+2)*HH + col], w3w = W1[(64+d4*4+3)*HH + col];
        #pragma unroll
        for (int r = 0; r < 8; ++r) {
            float4 xv = xr[(half*8 + r)*16 + d4];   // broadcast LDS
            a0[r] += xv.x*w0x + xv.y*w0y + xv.z*w0z + xv.w*w0w;
            a1[r] += xv.x*w1x + xv.y*w1y + xv.z*w1z + xv.w*w1w;
            a2[r] += xv.x*w2x + xv.y*w2y + xv.z*w2z + xv.w*w2w;
            a3[r] += xv.x*w3x + xv.y*w3y + xv.z*w3z + xv.w*w3w;
        }
    }
    #pragma unroll
    for (int r = 0; r < 8; ++r) {
        int row = row0 + half*8 + r;
        g_AI[row*HH + col] = a0[r];
        g_AJ[row*HH + col] = a1[r] + biasAJ;
        g_WI[row*HH + col] = a2[r];
        g_WJ[row*HH + col] = a3[r] + biasWJ;
    }
}

// ---------------- fused pair + update kernel: 256 threads, compacted j ----------------
// 256 blocks (32 b x 8 i-tiles of 16), 256 threads, ~84KB smem -> 2 blocks/SM.
// SMEM floats:
//   tab : [0, 16512)       compacted [jj<cnt][h=128] stride 129 (AJ, then WJ);
//                          after pass2: xr[0..1024) aggs[1024..3072) us[3072..5120)
//   hsb : [16512, 18560)   pass1 aiT [h][16]  ->  pass2 output hs [r=16][128]
//   attn: [18560, 20608)   [jj][16] compacted
//   a2s : [20608, 20736)
//   red : [20736, 20864)   [half][wq][8] x {max, sum}
//   jidx: [20864, 20992)   ints (compacted j list)
//   wcnt: [20992, 20996)   ints
#define SMF_FLOATS 20996
#define SMEM_FUSED (SMF_FLOATS * 4)
__global__ __launch_bounds__(256, 2)
void fused_kernel(const float* __restrict__ x, const float* __restrict__ A2,
                  const int* __restrict__ masks,
                  const float* __restrict__ W2, const float* __restrict__ b2,
                  const float* __restrict__ U1, const float* __restrict__ ub1,
                  const float* __restrict__ U2, const float* __restrict__ ub2,
                  float* __restrict__ out) {
    extern __shared__ __align__(16) float sm[];
    float* tab  = sm;
    float* hsb  = sm + 16512;   // aiT during pass1, hs after pass2
    float* attn = sm + 18560;
    float* a2s  = sm + 20608;
    float* red  = sm + 20736;
    int*   jidx = (int*)(sm + 20864);
    int*   wcnt = (int*)(sm + 20992);

    int t = threadIdx.x;
    int c128 = t & 127;
    int half = t >> 7;          // 0/1 -> 8 i's each
    int lane = t & 31;
    int wq = (t >> 5) & 3;      // warp within half
    int b  = blockIdx.x >> 3;
    int i0 = (blockIdx.x & 7) * 16;
    int rowbase = b*NN + i0;

    // preload x tile into registers (16 rows x 64 = 1024 floats)
    float xreg[4];
    #pragma unroll
    for (int k = 0; k < 4; ++k) xreg[k] = x[rowbase*DD + k*256 + t];

    // ---- mask compaction (warps 0-3 only) ----
    bool act = false;
    int prior = 0;
    if (t < 128) {
        act = masks[b*NN + t] != 0;
        unsigned bal = __ballot_sync(0xffffffffu, act);
        prior = __popc(bal & ((1u << lane) - 1u));
        if (lane == 0) wcnt[t >> 5] = __popc(bal);
        a2s[t] = A2[t];
    }
    int cnt = __syncthreads_count(t < 128 && act);   // barrier: wcnt visible
    float sa = (cnt > 0) ? 1.0f : 0.0f;
    if (t < 128 && act) {
        int w = t >> 5;
        int off = 0;
        #pragma unroll
        for (int ww = 0; ww < 3; ++ww) if (ww < w) off += wcnt[ww];
        jidx[off + prior] = t;
    }
    // aiT[h=c128][ii] for this half's 8 i's (independent of jidx)
    const float* AIb = g_AI + rowbase*HH;
    #pragma unroll
    for (int k = 0; k < 8; ++k)
        hsb[c128*16 + half*8 + k] = AIb[(half*8 + k)*HH + c128];
    __syncthreads();   // jidx visible

    // ---- compacted AJ table: tab[jj][h] for jj < cnt ----
    const float* AJb = g_AJ + b*NN*HH;
    {
        int tot = cnt << 7;
        #pragma unroll 4
        for (int idx = t; idx < tot; idx += 256) {
            int jj = idx >> 7, h = idx & 127;
            tab[jj*129 + h] = AJb[jidx[jj]*HH + h];
        }
    }
    __syncthreads();

    // ---- PASS 1: logits; thread = (compact slot c128, half: 8 i's) ----
    bool slot = (c128 < cnt);
    float l[8];
    #pragma unroll
    for (int k = 0; k < 8; ++k) l[k] = -1e30f;
    if (slot) {
        #pragma unroll
        for (int k = 0; k < 8; ++k) l[k] = 0.f;
        const float* tp = tab + c128*129;
        const float* sp = hsb + half*8;
        #pragma unroll 4
        for (int h = 0; h < HH; ++h) {
            float av  = tp[h];
            float a2v = a2s[h];
            float4 s0 = *(const float4*)(sp + h*16);       // broadcast LDS.128
            float4 s1 = *(const float4*)(sp + h*16 + 4);
            l[0] = fmaf(fmaxf(av + s0.x, 0.f), a2v, l[0]);
            l[1] = fmaf(fmaxf(av + s0.y, 0.f), a2v, l[1]);
            l[2] = fmaf(fmaxf(av + s0.z, 0.f), a2v, l[2]);
            l[3] = fmaf(fmaxf(av + s0.w, 0.f), a2v, l[3]);
            l[4] = fmaf(fmaxf(av + s1.x, 0.f), a2v, l[4]);
            l[5] = fmaf(fmaxf(av + s1.y, 0.f), a2v, l[5]);
            l[6] = fmaf(fmaxf(av + s1.z, 0.f), a2v, l[6]);
            l[7] = fmaf(fmaxf(av + s1.w, 0.f), a2v, l[7]);
        }
    }
    // reduce over compact slots within each half (4 warps)
    {
        #pragma unroll
        for (int k = 0; k < 8; ++k) {
            float v = l[k];
            #pragma unroll
            for (int off = 16; off; off >>= 1) v = fmaxf(v, __shfl_xor_sync(0xffffffffu, v, off));
            if (lane == 0) red[half*32 + wq*8 + k] = v;
        }
    }
    __syncthreads();
    float e[8];
    {
        const float* rb = red + half*32;
        #pragma unroll
        for (int k = 0; k < 8; ++k) {
            float mm = fmaxf(fmaxf(rb[k], rb[8+k]), fmaxf(rb[16+k], rb[24+k]));
            e[k] = slot ? __expf(l[k] - mm) : 0.f;
        }
        #pragma unroll
        for (int k = 0; k < 8; ++k) {
            float v = e[k];
            #pragma unroll
            for (int off = 16; off; off >>= 1) v += __shfl_xor_sync(0xffffffffu, v, off);
            if (lane == 0) red[64 + half*32 + wq*8 + k] = v;
        }
    }
    __syncthreads();
    if (slot) {
        const float* rb = red + 64 + half*32;
        #pragma unroll
        for (int k = 0; k < 8; ++k) {
            float ss = rb[k] + rb[8+k] + rb[16+k] + rb[24+k];
            attn[c128*16 + half*8 + k] = e[k] / ss;
        }
    }
    __syncthreads();   // attn done; pass1 table reads done

    // ---- compacted WJ table ----
    const float* WJb = g_WJ + b*NN*HH;
    {
        int tot = cnt << 7;
        #pragma unroll 4
        for (int idx = t; idx < tot; idx += 256) {
            int jj = idx >> 7, h = idx & 127;
            tab[jj*129 + h] = WJb[jidx[jj]*HH + h];
        }
    }
    __syncthreads();

    // ---- PASS 2: weighted hidden sum over cnt active j; thread = (h=c128, half: 8 i's) ----
    {
        const float* WIb = g_WI + rowbase*HH;
        float wi[8], hc[8];
        #pragma unroll
        for (int k = 0; k < 8; ++k) {
            wi[k] = WIb[(half*8 + k)*HH + c128];
            hc[k] = 0.f;
        }
        const float* tp = tab + c128;
        const float* ap = attn + half*8;
        #pragma unroll 4
        for (int jj = 0; jj < cnt; ++jj) {
            float wv = tp[jj*129];                          // conflict-free scalar
            float4 a0 = *(const float4*)(ap + jj*16);       // broadcast LDS.128
            float4 a1 = *(const float4*)(ap + jj*16 + 4);
            hc[0] = fmaf(a0.x, fmaxf(wi[0] + wv, 0.f), hc[0]);
            hc[1] = fmaf(a0.y, fmaxf(wi[1] + wv, 0.f), hc[1]);
            hc[2] = fmaf(a0.z, fmaxf(wi[2] + wv, 0.f), hc[2]);
            hc[3] = fmaf(a0.w, fmaxf(wi[3] + wv, 0.f), hc[3]);
            hc[4] = fmaf(a1.x, fmaxf(wi[4] + wv, 0.f), hc[4]);
            hc[5] = fmaf(a1.y, fmaxf(wi[5] + wv, 0.f), hc[5]);
            hc[6] = fmaf(a1.z, fmaxf(wi[6] + wv, 0.f), hc[6]);
            hc[7] = fmaf(a1.w, fmaxf(wi[7] + wv, 0.f), hc[7]);
        }
        #pragma unroll
        for (int k = 0; k < 8; ++k) hsb[(half*8 + k)*128 + c128] = hc[k];
    }
    __syncthreads();   // hs complete; tab free

    // ---- UPDATE phases (overlay xr/aggs/us onto tab; f32x2 packed FMA) ----
    float* xr   = tab;          // 1024 floats [r=16][64]
    float* aggs = tab + 1024;   // 2048 floats [r][128]
    float* us   = tab + 3072;   // 2048 floats [r][128]

    #pragma unroll
    for (int k = 0; k < 4; ++k) xr[k*256 + t] = xreg[k];

    // Phase A: agg[r][col] = hs[r] @ W2[:,col] + b2[col]*sa   (8 rows/thread, packed)
    {
        float b2v = b2[c128];
        u64 axy[8], azw[8];
        #pragma unroll
        for (int k = 0; k < 8; ++k) { axy[k] = 0ull; azw[k] = 0ull; }
        const float4* hs4 = (const float4*)hsb;
        #pragma unroll 4
        for (int h4 = 0; h4 < 32; ++h4) {
            float wx = W2[(h4*4+0)*HH + c128];
            float wy = W2[(h4*4+1)*HH + c128];
            float wz = W2[(h4*4+2)*HH + c128];
            float ww = W2[(h4*4+3)*HH + c128];
            u64 wxy, wzw; PACK2(wxy, wx, wy); PACK2(wzw, wz, ww);
            #pragma unroll
            for (int k = 0; k < 8; ++k) {
                F4U hv; hv.f = hs4[(half*8 + k)*32 + h4];   // broadcast LDS
                FMA2(axy[k], hv.u[0], wxy);
                FMA2(azw[k], hv.u[1], wzw);
            }
        }
        #pragma unroll
        for (int k = 0; k < 8; ++k) {
            u64 s; ADD2(s, axy[k], azw[k]);
            float lo, hi; UNPACK2(lo, hi, s);
            aggs[(half*8 + k)*128 + c128] = b2v*sa + lo + hi;
        }
    }
    __syncthreads();

    // Phase B: us[r][col] = relu([x_r, agg_r] @ U1[:,col] + ub1[col])  (packed, split loops)
    {
        float ubv = ub1[c128];
        u64 axy[8], azw[8];
        #pragma unroll
        for (int k = 0; k < 8; ++k) { axy[k] = 0ull; azw[k] = 0ull; }
        const float4* xr4 = (const float4*)xr;
        const float4* ag4 = (const float4*)aggs;
        #pragma unroll 4
        for (int c4 = 0; c4 < 16; ++c4) {
            float wx = U1[(c4*4+0)*HH + c128];
            float wy = U1[(c4*4+1)*HH + c128];
            float wz = U1[(c4*4+2)*HH + c128];
            float ww = U1[(c4*4+3)*HH + c128];
            u64 wxy, wzw; PACK2(wxy, wx, wy); PACK2(wzw, wz, ww);
            #pragma unroll
            for (int k = 0; k < 8; ++k) {
                F4U cv; cv.f = xr4[(half*8 + k)*16 + c4];
                FMA2(axy[k], cv.u[0], wxy);
                FMA2(azw[k], cv.u[1], wzw);
            }
        }
        #pragma unroll 4
        for (int c4 = 0; c4 < 32; ++c4) {
            float wx = U1[(64 + c4*4+0)*HH + c128];
            float wy = U1[(64 + c4*4+1)*HH + c128];
            float wz = U1[(64 + c4*4+2)*HH + c128];
            float ww = U1[(64 + c4*4+3)*HH + c128];
            u64 wxy, wzw; PACK2(wxy, wx, wy); PACK2(wzw, wz, ww);
            #pragma unroll
            for (int k = 0; k < 8; ++k) {
                F4U cv; cv.f = ag4[(half*8 + k)*32 + c4];
                FMA2(axy[k], cv.u[0], wxy);
                FMA2(azw[k], cv.u[1], wzw);
            }
        }
        #pragma unroll
        for (int k = 0; k < 8; ++k) {
            u64 s; ADD2(s, axy[k], azw[k]);
            float lo, hi; UNPACK2(lo, hi, s);
            us[(half*8 + k)*128 + c128] = fmaxf(ubv + lo + hi, 0.f);
        }
    }
    __syncthreads();

    // Phase C: out[r][col] = x[r][col] + us[r] @ U2[:,col] + ub2[col]  (4 rows/thread, packed)
    {
        int col = t & 63;
        int rg  = t >> 6;            // 0..3 -> rows rg*4 .. rg*4+3
        float ub2v = ub2[col];
        u64 axy[4], azw[4];
        #pragma unroll
        for (int k = 0; k < 4; ++k) { axy[k] = 0ull; azw[k] = 0ull; }
        const float4* us4 = (const float4*)us;
        #pragma unroll 4
        for (int k4 = 0; k4 < 32; ++k4) {
            float wx = U2[(k4*4+0)*DD + col];
            float wy = U2[(k4*4+1)*DD + col];
            float wz = U2[(k4*4+2)*DD + col];
            float ww = U2[(k4*4+3)*DD + col];
            u64 wxy, wzw; PACK2(wxy, wx, wy); PACK2(wzw, wz, ww);
            #pragma unroll
            for (int k = 0; k < 4; ++k) {
                F4U uv; uv.f = us4[(rg*4 + k)*32 + k4];   // broadcast
                FMA2(axy[k], uv.u[0], wxy);
                FMA2(azw[k], uv.u[1], wzw);
            }
        }
        #pragma unroll
        for (int k = 0; k < 4; ++k) {
            int r = rg*4 + k;
            u64 s; ADD2(s, axy[k], azw[k]);
            float lo, hi; UNPACK2(lo, hi, s);
            out[(rowbase + r)*DD + col] = xr[r*64 + col] + ub2v + lo + hi;
        }
    }
}

// ---------------- launch ----------------
extern "C" void kernel_launch(void* const* d_in, const int* in_sizes, int n_in,
                              void* d_out, int out_size) {
    const float* x    = (const float*)d_in[0];
    const int*   masks= (const int*)  d_in[1];
    const float* W1   = (const float*)d_in[2];
    const float* b1   = (const float*)d_in[3];
    const float* W2   = (const float*)d_in[4];
    const float* b2   = (const float*)d_in[5];
    const float* A1   = (const float*)d_in[6];
    const float* ab1  = (const float*)d_in[7];
    const float* A2   = (const float*)d_in[8];
    // d_in[9] = ab2: cancels in softmax
    const float* U1   = (const float*)d_in[10];
    const float* ub1  = (const float*)d_in[11];
    const float* U2   = (const float*)d_in[12];
    const float* ub2  = (const float*)d_in[13];
    float* out = (float*)d_out;

    cudaFuncSetAttribute(fused_kernel, cudaFuncAttributeMaxDynamicSharedMemorySize, SMEM_FUSED);

    proj_kernel<<<NROWS/16, 256>>>(x, A1, W1, b1, ab1);
    fused_kernel<<<BB*8, 256, SMEM_FUSED>>>(x, A2, masks, W2, b2, U1, ub1, U2, ub2, out);
}